// round 2
// baseline (speedup 1.0000x reference)
#include <cuda_runtime.h>

#define N_NODES 100000
#define HID 128
#define NUM_IN 32
#define IN_DIM 71
#define LN_EPS 1e-5f

// ---- scratch (device globals; no allocation allowed) ----
__device__ __align__(16) float g_x[N_NODES * HID];    // node features (updated in place per layer)
__device__ __align__(16) float g_agg[N_NODES * HID];  // neighbor sum
__device__ float g_cnt[N_NODES];                      // in-degree (float)

// ------------------------------------------------------------------
// zero g_agg (and g_cnt when zero_cnt != 0)
// ------------------------------------------------------------------
__global__ void zero_kernel(int zero_cnt) {
    int i = blockIdx.x * blockDim.x + threadIdx.x;
    int stride = gridDim.x * blockDim.x;
    float4 z = make_float4(0.f, 0.f, 0.f, 0.f);
    float4* a4 = reinterpret_cast<float4*>(g_agg);
    const int n4 = N_NODES * HID / 4;
    for (int idx = i; idx < n4; idx += stride) a4[idx] = z;
    if (zero_cnt) {
        for (int idx = i; idx < N_NODES; idx += stride) g_cnt[idx] = 0.f;
    }
}

// ------------------------------------------------------------------
// input: x = relu(concat(x_num, emb lookups) @ w_in + b_in)
// block: 128 threads, 16 nodes/block. w_in (71x128) staged in smem.
// ------------------------------------------------------------------
__global__ __launch_bounds__(128) void input_kernel(
    const float* __restrict__ x_num, const int* __restrict__ x_cat,
    const float* __restrict__ emb0, const float* __restrict__ emb1,
    const float* __restrict__ emb2, const float* __restrict__ emb3,
    const float* __restrict__ w_in, const float* __restrict__ b_in)
{
    __shared__ float ws[IN_DIM * HID];   // 36352 B
    __shared__ float ins[16 * 72];       // 4608 B
    int tid = threadIdx.x;
    for (int i = tid; i < IN_DIM * HID; i += 128) ws[i] = w_in[i];

    int node0 = blockIdx.x * 16;
    // numeric part
    for (int i = tid; i < 16 * NUM_IN; i += 128) {
        int n = i / NUM_IN, k = i % NUM_IN;
        int node = node0 + n;
        ins[n * 72 + k] = (node < N_NODES) ? x_num[node * NUM_IN + k] : 0.f;
    }
    // embedding part (10 + 6 + 5 + 18 = 39)
    for (int i = tid; i < 16 * 39; i += 128) {
        int n = i / 39, j = i % 39;
        int node = node0 + n;
        float v = 0.f;
        if (node < N_NODES) {
            if (j < 10)      v = emb0[x_cat[node * 4 + 0] * 10 + j];
            else if (j < 16) v = emb1[x_cat[node * 4 + 1] * 6 + (j - 10)];
            else if (j < 21) v = emb2[x_cat[node * 4 + 2] * 5 + (j - 16)];
            else             v = emb3[x_cat[node * 4 + 3] * 18 + (j - 21)];
        }
        ins[n * 72 + NUM_IN + j] = v;
    }
    __syncthreads();

    float acc[16];
#pragma unroll
    for (int n = 0; n < 16; n++) acc[n] = 0.f;
    for (int k = 0; k < IN_DIM; k++) {
        float w = ws[k * HID + tid];
#pragma unroll
        for (int n = 0; n < 16; n++) acc[n] += ins[n * 72 + k] * w;
    }
    float b = b_in[tid];
#pragma unroll
    for (int n = 0; n < 16; n++) {
        int node = node0 + n;
        if (node < N_NODES) g_x[node * HID + tid] = fmaxf(acc[n] + b, 0.f);
    }
}

// ------------------------------------------------------------------
// degree count (once; reused by both layers)
// ------------------------------------------------------------------
__global__ void count_kernel(const int* __restrict__ dst, int E) {
    int i = blockIdx.x * blockDim.x + threadIdx.x;
    if (i < E) atomicAdd(&g_cnt[dst[i]], 1.0f);
}

// ------------------------------------------------------------------
// scatter: agg[dst] += x[src]  (1 warp handles 4 edges; 128B per edge lane set)
// ------------------------------------------------------------------
__global__ __launch_bounds__(256) void scatter_kernel(
    const int* __restrict__ src, const int* __restrict__ dst, int E)
{
    int warp = (blockIdx.x * blockDim.x + threadIdx.x) >> 5;
    int lane = threadIdx.x & 31;
    const float4* x4 = reinterpret_cast<const float4*>(g_x);
    float4* a4 = reinterpret_cast<float4*>(g_agg);
    int e0 = warp * 4;
#pragma unroll
    for (int q = 0; q < 4; q++) {
        int e = e0 + q;
        if (e < E) {
            int s = __ldg(&src[e]);
            int d = __ldg(&dst[e]);
            float4 v = x4[(size_t)s * 32 + lane];
            float* addr = reinterpret_cast<float*>(&a4[(size_t)d * 32 + lane]);
            asm volatile("red.global.add.v4.f32 [%0], {%1,%2,%3,%4};"
                         :: "l"(addr), "f"(v.x), "f"(v.y), "f"(v.z), "f"(v.w)
                         : "memory");
        }
    }
}

// ------------------------------------------------------------------
// SAGE update (fused):
//   mean = agg / max(cnt,1)
//   o    = mean @ wl + bl + x @ wr         (GEMM: [BM,256] @ [256,128])
//   x    = x + 0.5 * relu(layernorm(o; g, be))   (in place, row-local)
// block: 256 threads (16x16), BM=64, full BN=128, BK=32.
// ------------------------------------------------------------------
__global__ __launch_bounds__(256) void sage_kernel(
    const float* __restrict__ wl, const float* __restrict__ bl,
    const float* __restrict__ wr,
    const float* __restrict__ gam, const float* __restrict__ bet)
{
    __shared__ float As[64 * 32];    // 8 KB
    __shared__ float Bs[32 * 128];   // 16 KB
    __shared__ float sInv[64];

    int tid = threadIdx.x;
    int row0 = blockIdx.x * 64;
    if (tid < 64) {
        int r = row0 + tid;
        float c = (r < N_NODES) ? g_cnt[r] : 1.f;
        sInv[tid] = 1.f / fmaxf(c, 1.f);
    }
    __syncthreads();

    int tx = tid & 15, ty = tid >> 4;
    float acc[4][8];
#pragma unroll
    for (int i = 0; i < 4; i++)
#pragma unroll
        for (int j = 0; j < 8; j++) acc[i][j] = 0.f;

    for (int kt = 0; kt < 8; kt++) {
        int kg0 = kt * 32;
        // load A tile: A[r][k] = (kg<128) ? agg*inv : x
#pragma unroll
        for (int p = 0; p < 8; p++) {
            int idx = tid + p * 256;
            int r = idx >> 5, k = idx & 31;
            int row = row0 + r;
            int kg = kg0 + k;
            float v = 0.f;
            if (row < N_NODES) {
                if (kg < 128) v = g_agg[(size_t)row * HID + kg] * sInv[r];
                else          v = g_x[(size_t)row * HID + (kg - 128)];
            }
            As[r * 32 + k] = v;
        }
        // load B tile: B[k][c] = (kg<128) ? wl : wr
#pragma unroll
        for (int p = 0; p < 16; p++) {
            int idx = tid + p * 256;
            int k = idx >> 7, c = idx & 127;
            int kg = kg0 + k;
            Bs[k * 128 + c] = (kg < 128) ? wl[kg * 128 + c]
                                         : wr[(kg - 128) * 128 + c];
        }
        __syncthreads();
#pragma unroll
        for (int k = 0; k < 32; k++) {
            float a[4];
#pragma unroll
            for (int i = 0; i < 4; i++) a[i] = As[(ty * 4 + i) * 32 + k];
            float4 b0 = *reinterpret_cast<const float4*>(&Bs[k * 128 + tx * 8]);
            float4 b1 = *reinterpret_cast<const float4*>(&Bs[k * 128 + tx * 8 + 4]);
            float b[8] = {b0.x, b0.y, b0.z, b0.w, b1.x, b1.y, b1.z, b1.w};
#pragma unroll
            for (int i = 0; i < 4; i++)
#pragma unroll
                for (int j = 0; j < 8; j++) acc[i][j] += a[i] * b[j];
        }
        __syncthreads();
    }

    // epilogue: +bias, LayerNorm over 128 cols (16-lane shfl reduce), relu, residual
    int cbase = tx * 8;
    float blv[8], gv[8], bev[8];
#pragma unroll
    for (int j = 0; j < 8; j++) {
        blv[j] = bl[cbase + j];
        gv[j]  = gam[cbase + j];
        bev[j] = bet[cbase + j];
    }
#pragma unroll
    for (int i = 0; i < 4; i++) {
        int row = row0 + ty * 4 + i;
        float v[8];
        float s = 0.f, s2 = 0.f;
#pragma unroll
        for (int j = 0; j < 8; j++) {
            v[j] = acc[i][j] + blv[j];
            s += v[j];
            s2 += v[j] * v[j];
        }
#pragma unroll
        for (int m = 8; m > 0; m >>= 1) {
            s  += __shfl_xor_sync(0xffffffffu, s,  m);
            s2 += __shfl_xor_sync(0xffffffffu, s2, m);
        }
        float mu  = s * (1.f / 128.f);
        float var = s2 * (1.f / 128.f) - mu * mu;
        float rs  = rsqrtf(var + LN_EPS);
        if (row < N_NODES) {
#pragma unroll
            for (int j = 0; j < 8; j++) {
                int c = cbase + j;
                float ln = (v[j] - mu) * rs * gv[j] + bev[j];
                float xo = g_x[(size_t)row * HID + c];
                g_x[(size_t)row * HID + c] = xo + 0.5f * fmaxf(ln, 0.f);
            }
        }
    }
}

// ------------------------------------------------------------------
// head: out = relu(x @ wh1 + bh1) @ wh2 + bh2   (fused; shfl for 64->1)
// block: 256 threads (16x16), BM=64, BN=64 (full), BK=32, TM=4, TN=4
// ------------------------------------------------------------------
__global__ __launch_bounds__(256) void head_kernel(
    const float* __restrict__ wh1, const float* __restrict__ bh1,
    const float* __restrict__ wh2, const float* __restrict__ bh2,
    float* __restrict__ out)
{
    __shared__ float As[64 * 32];   // 8 KB
    __shared__ float Bs[32 * 64];   // 8 KB
    int tid = threadIdx.x;
    int tx = tid & 15, ty = tid >> 4;
    int row0 = blockIdx.x * 64;

    float acc[4][4];
#pragma unroll
    for (int i = 0; i < 4; i++)
#pragma unroll
        for (int j = 0; j < 4; j++) acc[i][j] = 0.f;

    for (int kt = 0; kt < 4; kt++) {
        int kg0 = kt * 32;
#pragma unroll
        for (int p = 0; p < 8; p++) {
            int idx = tid + p * 256;
            int r = idx >> 5, k = idx & 31;
            int row = row0 + r;
            As[r * 32 + k] = (row < N_NODES) ? g_x[(size_t)row * HID + kg0 + k] : 0.f;
        }
#pragma unroll
        for (int p = 0; p < 8; p++) {
            int idx = tid + p * 256;
            int k = idx >> 6, c = idx & 63;
            Bs[k * 64 + c] = wh1[(kg0 + k) * 64 + c];
        }
        __syncthreads();
#pragma unroll
        for (int k = 0; k < 32; k++) {
            float a[4];
#pragma unroll
            for (int i = 0; i < 4; i++) a[i] = As[(ty * 4 + i) * 32 + k];
            float4 bv = *reinterpret_cast<const float4*>(&Bs[k * 64 + tx * 4]);
            float b[4] = {bv.x, bv.y, bv.z, bv.w};
#pragma unroll
            for (int i = 0; i < 4; i++)
#pragma unroll
                for (int j = 0; j < 4; j++) acc[i][j] += a[i] * b[j];
        }
        __syncthreads();
    }

    float b1v[4], w2v[4];
#pragma unroll
    for (int j = 0; j < 4; j++) {
        int c = tx * 4 + j;
        b1v[j] = bh1[c];
        w2v[j] = wh2[c];
    }
    float bo = bh2[0];
#pragma unroll
    for (int i = 0; i < 4; i++) {
        float p = 0.f;
#pragma unroll
        for (int j = 0; j < 4; j++)
            p += fmaxf(acc[i][j] + b1v[j], 0.f) * w2v[j];
#pragma unroll
        for (int m = 8; m > 0; m >>= 1)
            p += __shfl_xor_sync(0xffffffffu, p, m);
        int row = row0 + ty * 4 + i;
        if (tx == 0 && row < N_NODES) out[row] = p + bo;
    }
}

// ------------------------------------------------------------------
extern "C" void kernel_launch(void* const* d_in, const int* in_sizes, int n_in,
                              void* d_out, int out_size)
{
    const float* x_num = (const float*)d_in[0];
    const int*   x_cat = (const int*)d_in[1];
    const int*   edge  = (const int*)d_in[2];
    const float* emb0  = (const float*)d_in[3];
    const float* emb1  = (const float*)d_in[4];
    const float* emb2  = (const float*)d_in[5];
    const float* emb3  = (const float*)d_in[6];
    const float* w_in  = (const float*)d_in[7];
    const float* b_in  = (const float*)d_in[8];
    const float* w1l   = (const float*)d_in[9];
    const float* b1l   = (const float*)d_in[10];
    const float* w1r   = (const float*)d_in[11];
    const float* w2l   = (const float*)d_in[12];
    const float* b2l   = (const float*)d_in[13];
    const float* w2r   = (const float*)d_in[14];
    const float* g1    = (const float*)d_in[15];
    const float* be1   = (const float*)d_in[16];
    const float* g2    = (const float*)d_in[17];
    const float* be2   = (const float*)d_in[18];
    const float* wh1   = (const float*)d_in[19];
    const float* bh1   = (const float*)d_in[20];
    const float* wh2   = (const float*)d_in[21];
    const float* bh2   = (const float*)d_in[22];
    float* out = (float*)d_out;

    int E = in_sizes[2] / 2;
    const int* src = edge;
    const int* dst = edge + E;

    int node_blocks16 = (N_NODES + 15) / 16;
    int node_blocks64 = (N_NODES + 63) / 64;
    int scat_blocks   = (E + 31) / 32;   // 8 warps * 4 edges per block

    zero_kernel<<<2048, 256>>>(1);
    input_kernel<<<node_blocks16, 128>>>(x_num, x_cat, emb0, emb1, emb2, emb3, w_in, b_in);
    count_kernel<<<(E + 255) / 256, 256>>>(dst, E);

    // layer 1
    scatter_kernel<<<scat_blocks, 256>>>(src, dst, E);
    sage_kernel<<<node_blocks64, 256>>>(w1l, b1l, w1r, g1, be1);

    // layer 2
    zero_kernel<<<2048, 256>>>(0);
    scatter_kernel<<<scat_blocks, 256>>>(src, dst, E);
    sage_kernel<<<node_blocks64, 256>>>(w2l, b2l, w2r, g2, be2);

    head_kernel<<<node_blocks64, 256>>>(wh1, bh1, wh2, bh2, out);
}

// round 3
// speedup vs baseline: 1.0688x; 1.0688x over previous
#include <cuda_runtime.h>

#define N_NODES 100000
#define HID 128
#define NUM_IN 32
#define IN_DIM 71
#define LN_EPS 1e-5f

// ---- packed fp32x2 helpers (sm_103a FFMA2: full fp32 precision, 2x rate) ----
#define FMA2(acc, a, b) \
    asm("fma.rn.f32x2 %0, %1, %2, %0;" : "+l"(acc) : "l"(a), "l"(b))
#define PACK_DUP(dst, x) do { \
    unsigned int _u = __float_as_uint(x); \
    asm("mov.b64 %0, {%1,%1};" : "=l"(dst) : "r"(_u)); } while (0)
#define UNPACK2(lo, hi, v) do { \
    unsigned int _l, _h; \
    asm("mov.b64 {%0,%1}, %2;" : "=r"(_l), "=r"(_h) : "l"(v)); \
    lo = __uint_as_float(_l); hi = __uint_as_float(_h); } while (0)

typedef unsigned long long u64;

// ---- scratch (device globals; no allocation allowed) ----
__device__ __align__(16) float g_x[N_NODES * HID];    // node features (updated in place per layer)
__device__ __align__(16) float g_agg[N_NODES * HID];  // neighbor sum
__device__ float g_cnt[N_NODES];                      // in-degree (float)

// ------------------------------------------------------------------
// zero g_agg (and g_cnt when zero_cnt != 0)
// ------------------------------------------------------------------
__global__ void zero_kernel(int zero_cnt) {
    int i = blockIdx.x * blockDim.x + threadIdx.x;
    int stride = gridDim.x * blockDim.x;
    float4 z = make_float4(0.f, 0.f, 0.f, 0.f);
    float4* a4 = reinterpret_cast<float4*>(g_agg);
    const int n4 = N_NODES * HID / 4;
    for (int idx = i; idx < n4; idx += stride) a4[idx] = z;
    if (zero_cnt) {
        for (int idx = i; idx < N_NODES; idx += stride) g_cnt[idx] = 0.f;
    }
}

// ------------------------------------------------------------------
// input: x = relu(concat(x_num, emb lookups) @ w_in + b_in)
// block: 128 threads, 16 nodes/block. w_in (71x128) staged in smem.
// f32x2: accumulate node-pairs; insT stored k-major so node pairs are
// contiguous (ld.shared.v2 broadcast).
// ------------------------------------------------------------------
__global__ __launch_bounds__(128) void input_kernel(
    const float* __restrict__ x_num, const int* __restrict__ x_cat,
    const float* __restrict__ emb0, const float* __restrict__ emb1,
    const float* __restrict__ emb2, const float* __restrict__ emb3,
    const float* __restrict__ w_in, const float* __restrict__ b_in)
{
    __shared__ float ws[IN_DIM * HID];       // 36352 B
    __shared__ float insT[IN_DIM * 16];      // k-major: insT[k*16 + n], 4544 B
    int tid = threadIdx.x;
    for (int i = tid; i < IN_DIM * HID; i += 128) ws[i] = w_in[i];

    int node0 = blockIdx.x * 16;
    // numeric part
    for (int i = tid; i < 16 * NUM_IN; i += 128) {
        int n = i / NUM_IN, k = i % NUM_IN;
        int node = node0 + n;
        insT[k * 16 + n] = (node < N_NODES) ? x_num[node * NUM_IN + k] : 0.f;
    }
    // embedding part (10 + 6 + 5 + 18 = 39)
    for (int i = tid; i < 16 * 39; i += 128) {
        int n = i / 39, j = i % 39;
        int node = node0 + n;
        float v = 0.f;
        if (node < N_NODES) {
            if (j < 10)      v = emb0[x_cat[node * 4 + 0] * 10 + j];
            else if (j < 16) v = emb1[x_cat[node * 4 + 1] * 6 + (j - 10)];
            else if (j < 21) v = emb2[x_cat[node * 4 + 2] * 5 + (j - 16)];
            else             v = emb3[x_cat[node * 4 + 3] * 18 + (j - 21)];
        }
        insT[(NUM_IN + j) * 16 + n] = v;
    }
    __syncthreads();

    u64 acc2[8];
#pragma unroll
    for (int p = 0; p < 8; p++) acc2[p] = 0ull;

    for (int k = 0; k < IN_DIM; k++) {
        float w = ws[k * HID + tid];
        u64 w2; PACK_DUP(w2, w);
        const u64* ip = reinterpret_cast<const u64*>(&insT[k * 16]);
#pragma unroll
        for (int p = 0; p < 8; p++) {
            u64 in2 = ip[p];          // broadcast ld.shared.b64
            FMA2(acc2[p], w2, in2);
        }
    }
    float b = b_in[tid];
#pragma unroll
    for (int p = 0; p < 8; p++) {
        float lo, hi;
        UNPACK2(lo, hi, acc2[p]);
        int n0 = node0 + 2 * p;
        if (n0 < N_NODES)     g_x[(size_t)n0 * HID + tid]       = fmaxf(lo + b, 0.f);
        if (n0 + 1 < N_NODES) g_x[(size_t)(n0 + 1) * HID + tid] = fmaxf(hi + b, 0.f);
    }
}

// ------------------------------------------------------------------
// degree count (once; reused by both layers)
// ------------------------------------------------------------------
__global__ void count_kernel(const int* __restrict__ dst, int E) {
    int i = blockIdx.x * blockDim.x + threadIdx.x;
    if (i < E) atomicAdd(&g_cnt[dst[i]], 1.0f);
}

// ------------------------------------------------------------------
// scatter: agg[dst] += x[src]  (1 warp handles 4 edges) — LTS-bound floor
// ------------------------------------------------------------------
__global__ __launch_bounds__(256) void scatter_kernel(
    const int* __restrict__ src, const int* __restrict__ dst, int E)
{
    int warp = (blockIdx.x * blockDim.x + threadIdx.x) >> 5;
    int lane = threadIdx.x & 31;
    const float4* x4 = reinterpret_cast<const float4*>(g_x);
    float4* a4 = reinterpret_cast<float4*>(g_agg);
    int e0 = warp * 4;
#pragma unroll
    for (int q = 0; q < 4; q++) {
        int e = e0 + q;
        if (e < E) {
            int s = __ldg(&src[e]);
            int d = __ldg(&dst[e]);
            float4 v = x4[(size_t)s * 32 + lane];
            float* addr = reinterpret_cast<float*>(&a4[(size_t)d * 32 + lane]);
            asm volatile("red.global.add.v4.f32 [%0], {%1,%2,%3,%4};"
                         :: "l"(addr), "f"(v.x), "f"(v.y), "f"(v.z), "f"(v.w)
                         : "memory");
        }
    }
}

// ------------------------------------------------------------------
// SAGE update (fused), f32x2 inner loop:
//   mean = agg / max(cnt,1)
//   o    = mean @ wl + bl + x @ wr         (GEMM: [BM,256] @ [256,128])
//   x    = x + 0.5 * relu(layernorm(o; g, be))   (in place, row-local)
// block: 256 threads (16x16), BM=64, full BN=128, BK=32.
// ------------------------------------------------------------------
__global__ __launch_bounds__(256) void sage_kernel(
    const float* __restrict__ wl, const float* __restrict__ bl,
    const float* __restrict__ wr,
    const float* __restrict__ gam, const float* __restrict__ bet)
{
    __shared__ float As[64 * 32];    // 8 KB
    __shared__ float Bs[32 * 128];   // 16 KB
    __shared__ float sInv[64];

    int tid = threadIdx.x;
    int row0 = blockIdx.x * 64;
    if (tid < 64) {
        int r = row0 + tid;
        float c = (r < N_NODES) ? g_cnt[r] : 1.f;
        sInv[tid] = 1.f / fmaxf(c, 1.f);
    }
    __syncthreads();

    int tx = tid & 15, ty = tid >> 4;
    u64 acc2[4][4];   // [row i][col pair jp] -> cols (tx*8 + 2jp, +1)
#pragma unroll
    for (int i = 0; i < 4; i++)
#pragma unroll
        for (int j = 0; j < 4; j++) acc2[i][j] = 0ull;

    for (int kt = 0; kt < 8; kt++) {
        int kg0 = kt * 32;
        // load A tile: A[r][k] = (kg<128) ? agg*inv : x
#pragma unroll
        for (int p = 0; p < 8; p++) {
            int idx = tid + p * 256;
            int r = idx >> 5, k = idx & 31;
            int row = row0 + r;
            int kg = kg0 + k;
            float v = 0.f;
            if (row < N_NODES) {
                if (kg < 128) v = g_agg[(size_t)row * HID + kg] * sInv[r];
                else          v = g_x[(size_t)row * HID + (kg - 128)];
            }
            As[r * 32 + k] = v;
        }
        // load B tile: B[k][c] = (kg<128) ? wl : wr
#pragma unroll
        for (int p = 0; p < 16; p++) {
            int idx = tid + p * 256;
            int k = idx >> 7, c = idx & 127;
            int kg = kg0 + k;
            Bs[k * 128 + c] = (kg < 128) ? wl[kg * 128 + c]
                                         : wr[(kg - 128) * 128 + c];
        }
        __syncthreads();
#pragma unroll
        for (int k = 0; k < 32; k++) {
            u64 a2[4];
#pragma unroll
            for (int i = 0; i < 4; i++) {
                float a = As[(ty * 4 + i) * 32 + k];
                PACK_DUP(a2[i], a);
            }
            const u64* bp = reinterpret_cast<const u64*>(&Bs[k * 128 + tx * 8]);
            u64 b2[4];
            b2[0] = bp[0]; b2[1] = bp[1]; b2[2] = bp[2]; b2[3] = bp[3];
#pragma unroll
            for (int i = 0; i < 4; i++)
#pragma unroll
                for (int j = 0; j < 4; j++)
                    FMA2(acc2[i][j], a2[i], b2[j]);
        }
        __syncthreads();
    }

    // epilogue: +bias, LayerNorm over 128 cols (16-lane shfl reduce), relu, residual
    int cbase = tx * 8;
    float blv[8], gv[8], bev[8];
#pragma unroll
    for (int j = 0; j < 8; j++) {
        blv[j] = bl[cbase + j];
        gv[j]  = gam[cbase + j];
        bev[j] = bet[cbase + j];
    }
#pragma unroll
    for (int i = 0; i < 4; i++) {
        int row = row0 + ty * 4 + i;
        float v[8];
#pragma unroll
        for (int jp = 0; jp < 4; jp++)
            UNPACK2(v[2 * jp], v[2 * jp + 1], acc2[i][jp]);
        float s = 0.f, s2 = 0.f;
#pragma unroll
        for (int j = 0; j < 8; j++) {
            v[j] += blv[j];
            s += v[j];
            s2 += v[j] * v[j];
        }
#pragma unroll
        for (int m = 8; m > 0; m >>= 1) {
            s  += __shfl_xor_sync(0xffffffffu, s,  m);
            s2 += __shfl_xor_sync(0xffffffffu, s2, m);
        }
        float mu  = s * (1.f / 128.f);
        float var = s2 * (1.f / 128.f) - mu * mu;
        float rs  = rsqrtf(var + LN_EPS);
        if (row < N_NODES) {
#pragma unroll
            for (int j = 0; j < 8; j++) {
                int c = cbase + j;
                float ln = (v[j] - mu) * rs * gv[j] + bev[j];
                float xo = g_x[(size_t)row * HID + c];
                g_x[(size_t)row * HID + c] = xo + 0.5f * fmaxf(ln, 0.f);
            }
        }
    }
}

// ------------------------------------------------------------------
// head: out = relu(x @ wh1 + bh1) @ wh2 + bh2   (fused; shfl for 64->1)
// block: 256 threads (16x16), BM=64, BN=64 (full), BK=32, TM=4, TN=4
// ------------------------------------------------------------------
__global__ __launch_bounds__(256) void head_kernel(
    const float* __restrict__ wh1, const float* __restrict__ bh1,
    const float* __restrict__ wh2, const float* __restrict__ bh2,
    float* __restrict__ out)
{
    __shared__ float As[64 * 32];   // 8 KB
    __shared__ float Bs[32 * 64];   // 8 KB
    int tid = threadIdx.x;
    int tx = tid & 15, ty = tid >> 4;
    int row0 = blockIdx.x * 64;

    u64 acc2[4][2];
#pragma unroll
    for (int i = 0; i < 4; i++) { acc2[i][0] = 0ull; acc2[i][1] = 0ull; }

    for (int kt = 0; kt < 4; kt++) {
        int kg0 = kt * 32;
#pragma unroll
        for (int p = 0; p < 8; p++) {
            int idx = tid + p * 256;
            int r = idx >> 5, k = idx & 31;
            int row = row0 + r;
            As[r * 32 + k] = (row < N_NODES) ? g_x[(size_t)row * HID + kg0 + k] : 0.f;
        }
#pragma unroll
        for (int p = 0; p < 8; p++) {
            int idx = tid + p * 256;
            int k = idx >> 6, c = idx & 63;
            Bs[k * 64 + c] = wh1[(kg0 + k) * 64 + c];
        }
        __syncthreads();
#pragma unroll
        for (int k = 0; k < 32; k++) {
            u64 a2[4];
#pragma unroll
            for (int i = 0; i < 4; i++) {
                float a = As[(ty * 4 + i) * 32 + k];
                PACK_DUP(a2[i], a);
            }
            const u64* bp = reinterpret_cast<const u64*>(&Bs[k * 64 + tx * 4]);
            u64 b2[2];
            b2[0] = bp[0]; b2[1] = bp[1];
#pragma unroll
            for (int i = 0; i < 4; i++) {
                FMA2(acc2[i][0], a2[i], b2[0]);
                FMA2(acc2[i][1], a2[i], b2[1]);
            }
        }
        __syncthreads();
    }

    float b1v[4], w2v[4];
#pragma unroll
    for (int j = 0; j < 4; j++) {
        int c = tx * 4 + j;
        b1v[j] = bh1[c];
        w2v[j] = wh2[c];
    }
    float bo = bh2[0];
#pragma unroll
    for (int i = 0; i < 4; i++) {
        float a0, a1, a2v, a3;
        UNPACK2(a0, a1, acc2[i][0]);
        UNPACK2(a2v, a3, acc2[i][1]);
        float vv[4] = {a0, a1, a2v, a3};
        float p = 0.f;
#pragma unroll
        for (int j = 0; j < 4; j++)
            p += fmaxf(vv[j] + b1v[j], 0.f) * w2v[j];
#pragma unroll
        for (int m = 8; m > 0; m >>= 1)
            p += __shfl_xor_sync(0xffffffffu, p, m);
        int row = row0 + ty * 4 + i;
        if (tx == 0 && row < N_NODES) out[row] = p + bo;
    }
}

// ------------------------------------------------------------------
extern "C" void kernel_launch(void* const* d_in, const int* in_sizes, int n_in,
                              void* d_out, int out_size)
{
    const float* x_num = (const float*)d_in[0];
    const int*   x_cat = (const int*)d_in[1];
    const int*   edge  = (const int*)d_in[2];
    const float* emb0  = (const float*)d_in[3];
    const float* emb1  = (const float*)d_in[4];
    const float* emb2  = (const float*)d_in[5];
    const float* emb3  = (const float*)d_in[6];
    const float* w_in  = (const float*)d_in[7];
    const float* b_in  = (const float*)d_in[8];
    const float* w1l   = (const float*)d_in[9];
    const float* b1l   = (const float*)d_in[10];
    const float* w1r   = (const float*)d_in[11];
    const float* w2l   = (const float*)d_in[12];
    const float* b2l   = (const float*)d_in[13];
    const float* w2r   = (const float*)d_in[14];
    const float* g1    = (const float*)d_in[15];
    const float* be1   = (const float*)d_in[16];
    const float* g2    = (const float*)d_in[17];
    const float* be2   = (const float*)d_in[18];
    const float* wh1   = (const float*)d_in[19];
    const float* bh1   = (const float*)d_in[20];
    const float* wh2   = (const float*)d_in[21];
    const float* bh2   = (const float*)d_in[22];
    float* out = (float*)d_out;

    int E = in_sizes[2] / 2;
    const int* src = edge;
    const int* dst = edge + E;

    int node_blocks16 = (N_NODES + 15) / 16;
    int node_blocks64 = (N_NODES + 63) / 64;
    int scat_blocks   = (E + 31) / 32;   // 8 warps * 4 edges per block

    zero_kernel<<<2048, 256>>>(1);
    input_kernel<<<node_blocks16, 128>>>(x_num, x_cat, emb0, emb1, emb2, emb3, w_in, b_in);
    count_kernel<<<(E + 255) / 256, 256>>>(dst, E);

    // layer 1
    scatter_kernel<<<scat_blocks, 256>>>(src, dst, E);
    sage_kernel<<<node_blocks64, 256>>>(w1l, b1l, w1r, g1, be1);

    // layer 2
    zero_kernel<<<2048, 256>>>(0);
    scatter_kernel<<<scat_blocks, 256>>>(src, dst, E);
    sage_kernel<<<node_blocks64, 256>>>(w2l, b2l, w2r, g2, be2);

    head_kernel<<<node_blocks64, 256>>>(wh1, bh1, wh2, bh2, out);
}

// round 4
// speedup vs baseline: 1.0698x; 1.0010x over previous
#include <cuda_runtime.h>

#define N_NODES 100000
#define HID 128
#define NUM_IN 32
#define IN_DIM 71
#define LN_EPS 1e-5f

// ---- packed fp32x2 helpers (sm_103a FFMA2: full fp32 precision, 2x rate) ----
#define FMA2(acc, a, b) \
    asm("fma.rn.f32x2 %0, %1, %2, %0;" : "+l"(acc) : "l"(a), "l"(b))
#define PACK_DUP(dst, x) do { \
    unsigned int _u = __float_as_uint(x); \
    asm("mov.b64 %0, {%1,%1};" : "=l"(dst) : "r"(_u)); } while (0)
#define UNPACK2(lo, hi, v) do { \
    unsigned int _l, _h; \
    asm("mov.b64 {%0,%1}, %2;" : "=r"(_l), "=r"(_h) : "l"(v)); \
    lo = __uint_as_float(_l); hi = __uint_as_float(_h); } while (0)

typedef unsigned long long u64;

// ---- scratch (device globals; no allocation allowed) ----
__device__ __align__(16) float g_x[N_NODES * HID];    // node features (updated in place per layer)
__device__ __align__(16) float g_agg[N_NODES * HID];  // neighbor sum
__device__ float g_cnt[N_NODES];                      // in-degree (float)

// ------------------------------------------------------------------
// zero g_agg (and g_cnt when zero_cnt != 0)
// ------------------------------------------------------------------
__global__ void zero_kernel(int zero_cnt) {
    int i = blockIdx.x * blockDim.x + threadIdx.x;
    int stride = gridDim.x * blockDim.x;
    float4 z = make_float4(0.f, 0.f, 0.f, 0.f);
    float4* a4 = reinterpret_cast<float4*>(g_agg);
    const int n4 = N_NODES * HID / 4;
    for (int idx = i; idx < n4; idx += stride) a4[idx] = z;
    if (zero_cnt) {
        for (int idx = i; idx < N_NODES; idx += stride) g_cnt[idx] = 0.f;
    }
}

// ------------------------------------------------------------------
// input: x = relu(concat(x_num, emb lookups) @ w_in + b_in)
// block: 128 threads, 16 nodes/block. w_in (71x128) staged in smem.
// f32x2: accumulate node-pairs; insT stored k-major so node pairs are
// contiguous (ld.shared.v2 broadcast).
// ------------------------------------------------------------------
__global__ __launch_bounds__(128) void input_kernel(
    const float* __restrict__ x_num, const int* __restrict__ x_cat,
    const float* __restrict__ emb0, const float* __restrict__ emb1,
    const float* __restrict__ emb2, const float* __restrict__ emb3,
    const float* __restrict__ w_in, const float* __restrict__ b_in)
{
    __shared__ float ws[IN_DIM * HID];       // 36352 B
    __shared__ float insT[IN_DIM * 16];      // k-major: insT[k*16 + n], 4544 B
    int tid = threadIdx.x;
    for (int i = tid; i < IN_DIM * HID; i += 128) ws[i] = w_in[i];

    int node0 = blockIdx.x * 16;
    // numeric part
    for (int i = tid; i < 16 * NUM_IN; i += 128) {
        int n = i / NUM_IN, k = i % NUM_IN;
        int node = node0 + n;
        insT[k * 16 + n] = (node < N_NODES) ? x_num[node * NUM_IN + k] : 0.f;
    }
    // embedding part (10 + 6 + 5 + 18 = 39)
    for (int i = tid; i < 16 * 39; i += 128) {
        int n = i / 39, j = i % 39;
        int node = node0 + n;
        float v = 0.f;
        if (node < N_NODES) {
            if (j < 10)      v = emb0[x_cat[node * 4 + 0] * 10 + j];
            else if (j < 16) v = emb1[x_cat[node * 4 + 1] * 6 + (j - 10)];
            else if (j < 21) v = emb2[x_cat[node * 4 + 2] * 5 + (j - 16)];
            else             v = emb3[x_cat[node * 4 + 3] * 18 + (j - 21)];
        }
        insT[(NUM_IN + j) * 16 + n] = v;
    }
    __syncthreads();

    u64 acc2[8];
#pragma unroll
    for (int p = 0; p < 8; p++) acc2[p] = 0ull;

    for (int k = 0; k < IN_DIM; k++) {
        float w = ws[k * HID + tid];
        u64 w2; PACK_DUP(w2, w);
        const u64* ip = reinterpret_cast<const u64*>(&insT[k * 16]);
#pragma unroll
        for (int p = 0; p < 8; p++) {
            u64 in2 = ip[p];          // broadcast ld.shared.b64
            FMA2(acc2[p], w2, in2);
        }
    }
    float b = b_in[tid];
#pragma unroll
    for (int p = 0; p < 8; p++) {
        float lo, hi;
        UNPACK2(lo, hi, acc2[p]);
        int n0 = node0 + 2 * p;
        if (n0 < N_NODES)     g_x[(size_t)n0 * HID + tid]       = fmaxf(lo + b, 0.f);
        if (n0 + 1 < N_NODES) g_x[(size_t)(n0 + 1) * HID + tid] = fmaxf(hi + b, 0.f);
    }
}

// ------------------------------------------------------------------
// degree count (once; reused by both layers)
// ------------------------------------------------------------------
__global__ void count_kernel(const int* __restrict__ dst, int E) {
    int i = blockIdx.x * blockDim.x + threadIdx.x;
    if (i < E) atomicAdd(&g_cnt[dst[i]], 1.0f);
}

// ------------------------------------------------------------------
// scatter: agg[dst] += x[src]  (1 warp handles 4 edges) — LTS-bound floor
// ------------------------------------------------------------------
__global__ __launch_bounds__(256) void scatter_kernel(
    const int* __restrict__ src, const int* __restrict__ dst, int E)
{
    int warp = (blockIdx.x * blockDim.x + threadIdx.x) >> 5;
    int lane = threadIdx.x & 31;
    const float4* x4 = reinterpret_cast<const float4*>(g_x);
    float4* a4 = reinterpret_cast<float4*>(g_agg);
    int e0 = warp * 4;
#pragma unroll
    for (int q = 0; q < 4; q++) {
        int e = e0 + q;
        if (e < E) {
            int s = __ldg(&src[e]);
            int d = __ldg(&dst[e]);
            float4 v = x4[(size_t)s * 32 + lane];
            float* addr = reinterpret_cast<float*>(&a4[(size_t)d * 32 + lane]);
            asm volatile("red.global.add.v4.f32 [%0], {%1,%2,%3,%4};"
                         :: "l"(addr), "f"(v.x), "f"(v.y), "f"(v.z), "f"(v.w)
                         : "memory");
        }
    }
}

// ------------------------------------------------------------------
// SAGE update (fused), f32x2 inner loop:
//   mean = agg / max(cnt,1)
//   o    = mean @ wl + bl + x @ wr         (GEMM: [BM,256] @ [256,128])
//   x    = x + 0.5 * relu(layernorm(o; g, be))   (in place, row-local)
// block: 256 threads (16x16), BM=64, full BN=128, BK=32.
// ------------------------------------------------------------------
__global__ __launch_bounds__(256) void sage_kernel(
    const float* __restrict__ wl, const float* __restrict__ bl,
    const float* __restrict__ wr,
    const float* __restrict__ gam, const float* __restrict__ bet)
{
    __shared__ float As[64 * 32];    // 8 KB
    __shared__ float Bs[32 * 128];   // 16 KB
    __shared__ float sInv[64];

    int tid = threadIdx.x;
    int row0 = blockIdx.x * 64;
    if (tid < 64) {
        int r = row0 + tid;
        float c = (r < N_NODES) ? g_cnt[r] : 1.f;
        sInv[tid] = 1.f / fmaxf(c, 1.f);
    }
    __syncthreads();

    int tx = tid & 15, ty = tid >> 4;
    u64 acc2[4][4];   // [row i][col pair jp] -> cols (tx*8 + 2jp, +1)
#pragma unroll
    for (int i = 0; i < 4; i++)
#pragma unroll
        for (int j = 0; j < 4; j++) acc2[i][j] = 0ull;

    for (int kt = 0; kt < 8; kt++) {
        int kg0 = kt * 32;
        // load A tile: A[r][k] = (kg<128) ? agg*inv : x
#pragma unroll
        for (int p = 0; p < 8; p++) {
            int idx = tid + p * 256;
            int r = idx >> 5, k = idx & 31;
            int row = row0 + r;
            int kg = kg0 + k;
            float v = 0.f;
            if (row < N_NODES) {
                if (kg < 128) v = g_agg[(size_t)row * HID + kg] * sInv[r];
                else          v = g_x[(size_t)row * HID + (kg - 128)];
            }
            As[r * 32 + k] = v;
        }
        // load B tile: B[k][c] = (kg<128) ? wl : wr
#pragma unroll
        for (int p = 0; p < 16; p++) {
            int idx = tid + p * 256;
            int k = idx >> 7, c = idx & 127;
            int kg = kg0 + k;
            Bs[k * 128 + c] = (kg < 128) ? wl[kg * 128 + c]
                                         : wr[(kg - 128) * 128 + c];
        }
        __syncthreads();
#pragma unroll
        for (int k = 0; k < 32; k++) {
            u64 a2[4];
#pragma unroll
            for (int i = 0; i < 4; i++) {
                float a = As[(ty * 4 + i) * 32 + k];
                PACK_DUP(a2[i], a);
            }
            const u64* bp = reinterpret_cast<const u64*>(&Bs[k * 128 + tx * 8]);
            u64 b2[4];
            b2[0] = bp[0]; b2[1] = bp[1]; b2[2] = bp[2]; b2[3] = bp[3];
#pragma unroll
            for (int i = 0; i < 4; i++)
#pragma unroll
                for (int j = 0; j < 4; j++)
                    FMA2(acc2[i][j], a2[i], b2[j]);
        }
        __syncthreads();
    }

    // epilogue: +bias, LayerNorm over 128 cols (16-lane shfl reduce), relu, residual
    int cbase = tx * 8;
    float blv[8], gv[8], bev[8];
#pragma unroll
    for (int j = 0; j < 8; j++) {
        blv[j] = bl[cbase + j];
        gv[j]  = gam[cbase + j];
        bev[j] = bet[cbase + j];
    }
#pragma unroll
    for (int i = 0; i < 4; i++) {
        int row = row0 + ty * 4 + i;
        float v[8];
#pragma unroll
        for (int jp = 0; jp < 4; jp++)
            UNPACK2(v[2 * jp], v[2 * jp + 1], acc2[i][jp]);
        float s = 0.f, s2 = 0.f;
#pragma unroll
        for (int j = 0; j < 8; j++) {
            v[j] += blv[j];
            s += v[j];
            s2 += v[j] * v[j];
        }
#pragma unroll
        for (int m = 8; m > 0; m >>= 1) {
            s  += __shfl_xor_sync(0xffffffffu, s,  m);
            s2 += __shfl_xor_sync(0xffffffffu, s2, m);
        }
        float mu  = s * (1.f / 128.f);
        float var = s2 * (1.f / 128.f) - mu * mu;
        float rs  = rsqrtf(var + LN_EPS);
        if (row < N_NODES) {
#pragma unroll
            for (int j = 0; j < 8; j++) {
                int c = cbase + j;
                float ln = (v[j] - mu) * rs * gv[j] + bev[j];
                float xo = g_x[(size_t)row * HID + c];
                g_x[(size_t)row * HID + c] = xo + 0.5f * fmaxf(ln, 0.f);
            }
        }
    }
}

// ------------------------------------------------------------------
// head: out = relu(x @ wh1 + bh1) @ wh2 + bh2   (fused; shfl for 64->1)
// block: 256 threads (16x16), BM=64, BN=64 (full), BK=32, TM=4, TN=4
// ------------------------------------------------------------------
__global__ __launch_bounds__(256) void head_kernel(
    const float* __restrict__ wh1, const float* __restrict__ bh1,
    const float* __restrict__ wh2, const float* __restrict__ bh2,
    float* __restrict__ out)
{
    __shared__ float As[64 * 32];   // 8 KB
    __shared__ float Bs[32 * 64];   // 8 KB
    int tid = threadIdx.x;
    int tx = tid & 15, ty = tid >> 4;
    int row0 = blockIdx.x * 64;

    u64 acc2[4][2];
#pragma unroll
    for (int i = 0; i < 4; i++) { acc2[i][0] = 0ull; acc2[i][1] = 0ull; }

    for (int kt = 0; kt < 4; kt++) {
        int kg0 = kt * 32;
#pragma unroll
        for (int p = 0; p < 8; p++) {
            int idx = tid + p * 256;
            int r = idx >> 5, k = idx & 31;
            int row = row0 + r;
            As[r * 32 + k] = (row < N_NODES) ? g_x[(size_t)row * HID + kg0 + k] : 0.f;
        }
#pragma unroll
        for (int p = 0; p < 8; p++) {
            int idx = tid + p * 256;
            int k = idx >> 6, c = idx & 63;
            Bs[k * 64 + c] = wh1[(kg0 + k) * 64 + c];
        }
        __syncthreads();
#pragma unroll
        for (int k = 0; k < 32; k++) {
            u64 a2[4];
#pragma unroll
            for (int i = 0; i < 4; i++) {
                float a = As[(ty * 4 + i) * 32 + k];
                PACK_DUP(a2[i], a);
            }
            const u64* bp = reinterpret_cast<const u64*>(&Bs[k * 64 + tx * 4]);
            u64 b2[2];
            b2[0] = bp[0]; b2[1] = bp[1];
#pragma unroll
            for (int i = 0; i < 4; i++) {
                FMA2(acc2[i][0], a2[i], b2[0]);
                FMA2(acc2[i][1], a2[i], b2[1]);
            }
        }
        __syncthreads();
    }

    float b1v[4], w2v[4];
#pragma unroll
    for (int j = 0; j < 4; j++) {
        int c = tx * 4 + j;
        b1v[j] = bh1[c];
        w2v[j] = wh2[c];
    }
    float bo = bh2[0];
#pragma unroll
    for (int i = 0; i < 4; i++) {
        float a0, a1, a2v, a3;
        UNPACK2(a0, a1, acc2[i][0]);
        UNPACK2(a2v, a3, acc2[i][1]);
        float vv[4] = {a0, a1, a2v, a3};
        float p = 0.f;
#pragma unroll
        for (int j = 0; j < 4; j++)
            p += fmaxf(vv[j] + b1v[j], 0.f) * w2v[j];
#pragma unroll
        for (int m = 8; m > 0; m >>= 1)
            p += __shfl_xor_sync(0xffffffffu, p, m);
        int row = row0 + ty * 4 + i;
        if (tx == 0 && row < N_NODES) out[row] = p + bo;
    }
}

// ------------------------------------------------------------------
extern "C" void kernel_launch(void* const* d_in, const int* in_sizes, int n_in,
                              void* d_out, int out_size)
{
    const float* x_num = (const float*)d_in[0];
    const int*   x_cat = (const int*)d_in[1];
    const int*   edge  = (const int*)d_in[2];
    const float* emb0  = (const float*)d_in[3];
    const float* emb1  = (const float*)d_in[4];
    const float* emb2  = (const float*)d_in[5];
    const float* emb3  = (const float*)d_in[6];
    const float* w_in  = (const float*)d_in[7];
    const float* b_in  = (const float*)d_in[8];
    const float* w1l   = (const float*)d_in[9];
    const float* b1l   = (const float*)d_in[10];
    const float* w1r   = (const float*)d_in[11];
    const float* w2l   = (const float*)d_in[12];
    const float* b2l   = (const float*)d_in[13];
    const float* w2r   = (const float*)d_in[14];
    const float* g1    = (const float*)d_in[15];
    const float* be1   = (const float*)d_in[16];
    const float* g2    = (const float*)d_in[17];
    const float* be2   = (const float*)d_in[18];
    const float* wh1   = (const float*)d_in[19];
    const float* bh1   = (const float*)d_in[20];
    const float* wh2   = (const float*)d_in[21];
    const float* bh2   = (const float*)d_in[22];
    float* out = (float*)d_out;

    int E = in_sizes[2] / 2;
    const int* src = edge;
    const int* dst = edge + E;

    int node_blocks16 = (N_NODES + 15) / 16;
    int node_blocks64 = (N_NODES + 63) / 64;
    int scat_blocks   = (E + 31) / 32;   // 8 warps * 4 edges per block

    zero_kernel<<<2048, 256>>>(1);
    input_kernel<<<node_blocks16, 128>>>(x_num, x_cat, emb0, emb1, emb2, emb3, w_in, b_in);
    count_kernel<<<(E + 255) / 256, 256>>>(dst, E);

    // layer 1
    scatter_kernel<<<scat_blocks, 256>>>(src, dst, E);
    sage_kernel<<<node_blocks64, 256>>>(w1l, b1l, w1r, g1, be1);

    // layer 2
    zero_kernel<<<2048, 256>>>(0);
    scatter_kernel<<<scat_blocks, 256>>>(src, dst, E);
    sage_kernel<<<node_blocks64, 256>>>(w2l, b2l, w2r, g2, be2);

    head_kernel<<<node_blocks64, 256>>>(wh1, bh1, wh2, bh2, out);
}

// round 6
// speedup vs baseline: 1.2947x; 1.2102x over previous
#include <cuda_runtime.h>

#define N_NODES 100000
#define E_MAX   1600000
#define HID 128
#define NUM_IN 32
#define IN_DIM 71
#define LN_EPS 1e-5f
#define NB_SCAN ((N_NODES + 255) / 256)   // 391

// ---- packed fp32x2 helpers (sm_103a FFMA2: full fp32 precision, 2x rate) ----
#define FMA2(acc, a, b) \
    asm("fma.rn.f32x2 %0, %1, %2, %0;" : "+l"(acc) : "l"(a), "l"(b))
#define PACK_DUP(dst, x) do { \
    unsigned int _u = __float_as_uint(x); \
    asm("mov.b64 %0, {%1,%1};" : "=l"(dst) : "r"(_u)); } while (0)
#define UNPACK2(lo, hi, v) do { \
    unsigned int _l, _h; \
    asm("mov.b64 {%0,%1}, %2;" : "=r"(_l), "=r"(_h) : "l"(v)); \
    lo = __uint_as_float(_l); hi = __uint_as_float(_h); } while (0)

typedef unsigned long long u64;

// ---- scratch (device globals; no allocation allowed) ----
__device__ __align__(16) float g_xA[N_NODES * HID];   // ping
__device__ __align__(16) float g_xB[N_NODES * HID];   // pong
__device__ int g_deg[N_NODES];
__device__ int g_rowptr[N_NODES + 1];
__device__ int g_cursor[N_NODES];
__device__ int g_csr[E_MAX];                          // src ids grouped by dst
__device__ int g_bsum[512];
__device__ int g_boff[512];

// ------------------------------------------------------------------
// CSR build: zero deg -> histogram -> 2-level exclusive scan -> fill
// ------------------------------------------------------------------
__global__ void zero_deg_kernel() {
    int i = blockIdx.x * blockDim.x + threadIdx.x;
    if (i < N_NODES) g_deg[i] = 0;
}

__global__ void hist_kernel(const int* __restrict__ dst, int E) {
    int i = blockIdx.x * blockDim.x + threadIdx.x;
    if (i < E) atomicAdd(&g_deg[dst[i]], 1);
}

__global__ __launch_bounds__(256) void scan1_kernel() {
    int tid = threadIdx.x;
    int lane = tid & 31, wid = tid >> 5;
    int i = blockIdx.x * 256 + tid;
    int v = (i < N_NODES) ? g_deg[i] : 0;
    int x = v;
#pragma unroll
    for (int o = 1; o < 32; o <<= 1) {
        int y = __shfl_up_sync(0xffffffffu, x, o);
        if (lane >= o) x += y;
    }
    __shared__ int wsum[8];
    if (lane == 31) wsum[wid] = x;
    __syncthreads();
    if (tid == 0) {
        int run = 0;
#pragma unroll
        for (int w = 0; w < 8; w++) { int t = wsum[w]; wsum[w] = run; run += t; }
        g_bsum[blockIdx.x] = run;
    }
    __syncthreads();
    int excl = x - v + wsum[wid];
    if (i < N_NODES) g_rowptr[i] = excl;
}

__global__ __launch_bounds__(512) void scan2_kernel() {
    __shared__ int s[512];
    int tid = threadIdx.x;
    int v = (tid < NB_SCAN) ? g_bsum[tid] : 0;
    s[tid] = v;
    __syncthreads();
    for (int o = 1; o < 512; o <<= 1) {
        int t = (tid >= o) ? s[tid - o] : 0;
        __syncthreads();
        s[tid] += t;
        __syncthreads();
    }
    if (tid < NB_SCAN) g_boff[tid] = s[tid] - v;   // exclusive
}

__global__ void scan3_kernel(int E) {
    int i = blockIdx.x * blockDim.x + threadIdx.x;
    if (i < N_NODES) {
        int v = g_rowptr[i] + g_boff[blockIdx.x];
        g_rowptr[i] = v;
        g_cursor[i] = v;
    }
    if (i == 0) g_rowptr[N_NODES] = E;
}

__global__ void fill_kernel(const int* __restrict__ src, const int* __restrict__ dst, int E) {
    int i = blockIdx.x * blockDim.x + threadIdx.x;
    if (i < E) {
        int d = dst[i];
        int pos = atomicAdd(&g_cursor[d], 1);
        g_csr[pos] = src[i];
    }
}

// ------------------------------------------------------------------
// input: x = relu(concat(x_num, emb lookups) @ w_in + b_in)
// block: 128 threads, 32 nodes/block. w_in (71x128) staged in smem.
// ------------------------------------------------------------------
__global__ __launch_bounds__(128) void input_kernel(
    const float* __restrict__ x_num, const int* __restrict__ x_cat,
    const float* __restrict__ emb0, const float* __restrict__ emb1,
    const float* __restrict__ emb2, const float* __restrict__ emb3,
    const float* __restrict__ w_in, const float* __restrict__ b_in,
    float* __restrict__ xout)
{
    __shared__ float ws[IN_DIM * HID];       // 36352 B
    __shared__ float insT[IN_DIM * 32];      // k-major: insT[k*32 + n], 9088 B
    int tid = threadIdx.x;
    for (int i = tid; i < IN_DIM * HID; i += 128) ws[i] = w_in[i];

    int node0 = blockIdx.x * 32;
    // numeric part
    for (int i = tid; i < 32 * NUM_IN; i += 128) {
        int n = i / NUM_IN, k = i % NUM_IN;
        int node = node0 + n;
        insT[k * 32 + n] = (node < N_NODES) ? x_num[node * NUM_IN + k] : 0.f;
    }
    // embedding part (10 + 6 + 5 + 18 = 39)
    for (int i = tid; i < 32 * 39; i += 128) {
        int n = i / 39, j = i % 39;
        int node = node0 + n;
        float v = 0.f;
        if (node < N_NODES) {
            if (j < 10)      v = emb0[x_cat[node * 4 + 0] * 10 + j];
            else if (j < 16) v = emb1[x_cat[node * 4 + 1] * 6 + (j - 10)];
            else if (j < 21) v = emb2[x_cat[node * 4 + 2] * 5 + (j - 16)];
            else             v = emb3[x_cat[node * 4 + 3] * 18 + (j - 21)];
        }
        insT[(NUM_IN + j) * 32 + n] = v;
    }
    __syncthreads();

    u64 acc2[16];
#pragma unroll
    for (int p = 0; p < 16; p++) acc2[p] = 0ull;

    for (int k = 0; k < IN_DIM; k++) {
        float w = ws[k * HID + tid];
        u64 w2; PACK_DUP(w2, w);
        const u64* ip = reinterpret_cast<const u64*>(&insT[k * 32]);
#pragma unroll
        for (int p = 0; p < 16; p++) {
            u64 in2 = ip[p];          // broadcast ld.shared.b64
            FMA2(acc2[p], w2, in2);
        }
    }
    float b = b_in[tid];
#pragma unroll
    for (int p = 0; p < 16; p++) {
        float lo, hi;
        UNPACK2(lo, hi, acc2[p]);
        int n0 = node0 + 2 * p;
        if (n0 < N_NODES)     xout[(size_t)n0 * HID + tid]       = fmaxf(lo + b, 0.f);
        if (n0 + 1 < N_NODES) xout[(size_t)(n0 + 1) * HID + tid] = fmaxf(hi + b, 0.f);
    }
}

// ------------------------------------------------------------------
// SAGE update (gather + GEMM + LN fused), ping-pong safe:
//   reads xin (immutable this launch), writes xout.
//   phase 1: per-block gather of 64 dst rows via CSR -> mean into smem
//   phase 2: o = mean @ wl + bl + xin @ wr ; xout = xin + 0.5*relu(LN(o))
// block: 256 threads (16x16), BM=64, BN=128, BK=32.
// ------------------------------------------------------------------
__global__ __launch_bounds__(256) void sage_kernel(
    const float* __restrict__ xin, float* __restrict__ xout,
    const float* __restrict__ wl, const float* __restrict__ bl,
    const float* __restrict__ wr,
    const float* __restrict__ gam, const float* __restrict__ bet)
{
    __shared__ float sMean[64 * 128];  // 32 KB
    __shared__ float As[64 * 32];      // 8 KB (xin tile for kt>=4)
    __shared__ float Bs[32 * 128];     // 16 KB

    int tid = threadIdx.x;
    int row0 = blockIdx.x * 64;
    int warp = tid >> 5, lane = tid & 31;
    const float4* x4 = reinterpret_cast<const float4*>(xin);

    // ---- phase 1: gather mean (warp per row, 8 rows per warp) ----
#pragma unroll 1
    for (int j = 0; j < 8; j++) {
        int r = warp * 8 + j;
        int row = row0 + r;
        int beg = 0, end = 0;
        if (row < N_NODES) { beg = g_rowptr[row]; end = g_rowptr[row + 1]; }
        float4 a0 = make_float4(0.f, 0.f, 0.f, 0.f);
        float4 a1 = a0, a2 = a0, a3 = a0;
        int e = beg;
        for (; e + 4 <= end; e += 4) {
            int s0 = __ldg(&g_csr[e]);
            int s1 = __ldg(&g_csr[e + 1]);
            int s2 = __ldg(&g_csr[e + 2]);
            int s3 = __ldg(&g_csr[e + 3]);
            float4 v0 = x4[(size_t)s0 * 32 + lane];
            float4 v1 = x4[(size_t)s1 * 32 + lane];
            float4 v2 = x4[(size_t)s2 * 32 + lane];
            float4 v3 = x4[(size_t)s3 * 32 + lane];
            a0.x += v0.x; a0.y += v0.y; a0.z += v0.z; a0.w += v0.w;
            a1.x += v1.x; a1.y += v1.y; a1.z += v1.z; a1.w += v1.w;
            a2.x += v2.x; a2.y += v2.y; a2.z += v2.z; a2.w += v2.w;
            a3.x += v3.x; a3.y += v3.y; a3.z += v3.z; a3.w += v3.w;
        }
        for (; e < end; e++) {
            int s = __ldg(&g_csr[e]);
            float4 v = x4[(size_t)s * 32 + lane];
            a0.x += v.x; a0.y += v.y; a0.z += v.z; a0.w += v.w;
        }
        float inv = 1.f / fmaxf((float)(end - beg), 1.f);
        float4 m;
        m.x = (a0.x + a1.x + a2.x + a3.x) * inv;
        m.y = (a0.y + a1.y + a2.y + a3.y) * inv;
        m.z = (a0.z + a1.z + a2.z + a3.z) * inv;
        m.w = (a0.w + a1.w + a2.w + a3.w) * inv;
        reinterpret_cast<float4*>(sMean)[r * 32 + lane] = m;
    }
    __syncthreads();

    // ---- phase 2: GEMM ----
    int tx = tid & 15, ty = tid >> 4;
    u64 acc2[4][4];   // [row i][col pair jp] -> cols (tx*8 + 2jp, +1)
#pragma unroll
    for (int i = 0; i < 4; i++)
#pragma unroll
        for (int j = 0; j < 4; j++) acc2[i][j] = 0ull;

#pragma unroll 1
    for (int kt = 0; kt < 8; kt++) {
        int kg0 = kt * 32;
        // stage xin tile for kg>=128 (mean tile already resident in sMean)
        if (kt >= 4) {
#pragma unroll
            for (int p = 0; p < 8; p++) {
                int idx = tid + p * 256;
                int r = idx >> 5, k = idx & 31;
                int row = row0 + r;
                As[r * 32 + k] = (row < N_NODES)
                    ? xin[(size_t)row * HID + (kg0 - 128 + k)] : 0.f;
            }
        }
        // stage B tile: B[k][c] = (kg<128) ? wl : wr
#pragma unroll
        for (int p = 0; p < 16; p++) {
            int idx = tid + p * 256;
            int k = idx >> 7, c = idx & 127;
            int kg = kg0 + k;
            Bs[k * 128 + c] = (kg < 128) ? wl[kg * 128 + c]
                                         : wr[(kg - 128) * 128 + c];
        }
        __syncthreads();

        const float* Abase = (kt < 4) ? (sMean + kg0) : As;
        int astr = (kt < 4) ? 128 : 32;
#pragma unroll
        for (int k = 0; k < 32; k++) {
            u64 a2[4];
#pragma unroll
            for (int i = 0; i < 4; i++) {
                float a = Abase[(ty * 4 + i) * astr + k];
                PACK_DUP(a2[i], a);
            }
            const u64* bp = reinterpret_cast<const u64*>(&Bs[k * 128 + tx * 8]);
            u64 b2[4];
            b2[0] = bp[0]; b2[1] = bp[1]; b2[2] = bp[2]; b2[3] = bp[3];
#pragma unroll
            for (int i = 0; i < 4; i++)
#pragma unroll
                for (int j = 0; j < 4; j++)
                    FMA2(acc2[i][j], a2[i], b2[j]);
        }
        __syncthreads();
    }

    // epilogue: +bias, LayerNorm (16-lane shfl reduce), relu, residual
    int cbase = tx * 8;
    float blv[8], gv[8], bev[8];
#pragma unroll
    for (int j = 0; j < 8; j++) {
        blv[j] = bl[cbase + j];
        gv[j]  = gam[cbase + j];
        bev[j] = bet[cbase + j];
    }
#pragma unroll
    for (int i = 0; i < 4; i++) {
        int row = row0 + ty * 4 + i;
        float v[8];
#pragma unroll
        for (int jp = 0; jp < 4; jp++)
            UNPACK2(v[2 * jp], v[2 * jp + 1], acc2[i][jp]);
        float s = 0.f, s2 = 0.f;
#pragma unroll
        for (int j = 0; j < 8; j++) {
            v[j] += blv[j];
            s += v[j];
            s2 += v[j] * v[j];
        }
#pragma unroll
        for (int m = 8; m > 0; m >>= 1) {
            s  += __shfl_xor_sync(0xffffffffu, s,  m);
            s2 += __shfl_xor_sync(0xffffffffu, s2, m);
        }
        float mu  = s * (1.f / 128.f);
        float var = s2 * (1.f / 128.f) - mu * mu;
        float rs  = rsqrtf(var + LN_EPS);
        if (row < N_NODES) {
#pragma unroll
            for (int j = 0; j < 8; j++) {
                int c = cbase + j;
                float ln = (v[j] - mu) * rs * gv[j] + bev[j];
                float xo = xin[(size_t)row * HID + c];
                xout[(size_t)row * HID + c] = xo + 0.5f * fmaxf(ln, 0.f);
            }
        }
    }
}

// ------------------------------------------------------------------
// head: out = relu(x @ wh1 + bh1) @ wh2 + bh2   (fused; shfl for 64->1)
// ------------------------------------------------------------------
__global__ __launch_bounds__(256) void head_kernel(
    const float* __restrict__ xin,
    const float* __restrict__ wh1, const float* __restrict__ bh1,
    const float* __restrict__ wh2, const float* __restrict__ bh2,
    float* __restrict__ out)
{
    __shared__ float As[64 * 32];   // 8 KB
    __shared__ float Bs[32 * 64];   // 8 KB
    int tid = threadIdx.x;
    int tx = tid & 15, ty = tid >> 4;
    int row0 = blockIdx.x * 64;

    u64 acc2[4][2];
#pragma unroll
    for (int i = 0; i < 4; i++) { acc2[i][0] = 0ull; acc2[i][1] = 0ull; }

    for (int kt = 0; kt < 4; kt++) {
        int kg0 = kt * 32;
#pragma unroll
        for (int p = 0; p < 8; p++) {
            int idx = tid + p * 256;
            int r = idx >> 5, k = idx & 31;
            int row = row0 + r;
            As[r * 32 + k] = (row < N_NODES) ? xin[(size_t)row * HID + kg0 + k] : 0.f;
        }
#pragma unroll
        for (int p = 0; p < 8; p++) {
            int idx = tid + p * 256;
            int k = idx >> 6, c = idx & 63;
            Bs[k * 64 + c] = wh1[(kg0 + k) * 64 + c];
        }
        __syncthreads();
#pragma unroll
        for (int k = 0; k < 32; k++) {
            u64 a2[4];
#pragma unroll
            for (int i = 0; i < 4; i++) {
                float a = As[(ty * 4 + i) * 32 + k];
                PACK_DUP(a2[i], a);
            }
            const u64* bp = reinterpret_cast<const u64*>(&Bs[k * 64 + tx * 4]);
            u64 b2[2];
            b2[0] = bp[0]; b2[1] = bp[1];
#pragma unroll
            for (int i = 0; i < 4; i++) {
                FMA2(acc2[i][0], a2[i], b2[0]);
                FMA2(acc2[i][1], a2[i], b2[1]);
            }
        }
        __syncthreads();
    }

    float b1v[4], w2v[4];
#pragma unroll
    for (int j = 0; j < 4; j++) {
        int c = tx * 4 + j;
        b1v[j] = bh1[c];
        w2v[j] = wh2[c];
    }
    float bo = bh2[0];
#pragma unroll
    for (int i = 0; i < 4; i++) {
        float a0, a1, a2v, a3;
        UNPACK2(a0, a1, acc2[i][0]);
        UNPACK2(a2v, a3, acc2[i][1]);
        float vv[4] = {a0, a1, a2v, a3};
        float p = 0.f;
#pragma unroll
        for (int j = 0; j < 4; j++)
            p += fmaxf(vv[j] + b1v[j], 0.f) * w2v[j];
#pragma unroll
        for (int m = 8; m > 0; m >>= 1)
            p += __shfl_xor_sync(0xffffffffu, p, m);
        int row = row0 + ty * 4 + i;
        if (tx == 0 && row < N_NODES) out[row] = p + bo;
    }
}

// ------------------------------------------------------------------
extern "C" void kernel_launch(void* const* d_in, const int* in_sizes, int n_in,
                              void* d_out, int out_size)
{
    const float* x_num = (const float*)d_in[0];
    const int*   x_cat = (const int*)d_in[1];
    const int*   edge  = (const int*)d_in[2];
    const float* emb0  = (const float*)d_in[3];
    const float* emb1  = (const float*)d_in[4];
    const float* emb2  = (const float*)d_in[5];
    const float* emb3  = (const float*)d_in[6];
    const float* w_in  = (const float*)d_in[7];
    const float* b_in  = (const float*)d_in[8];
    const float* w1l   = (const float*)d_in[9];
    const float* b1l   = (const float*)d_in[10];
    const float* w1r   = (const float*)d_in[11];
    const float* w2l   = (const float*)d_in[12];
    const float* b2l   = (const float*)d_in[13];
    const float* w2r   = (const float*)d_in[14];
    const float* g1    = (const float*)d_in[15];
    const float* be1   = (const float*)d_in[16];
    const float* g2    = (const float*)d_in[17];
    const float* be2   = (const float*)d_in[18];
    const float* wh1   = (const float*)d_in[19];
    const float* bh1   = (const float*)d_in[20];
    const float* wh2   = (const float*)d_in[21];
    const float* bh2   = (const float*)d_in[22];
    float* out = (float*)d_out;

    int E = in_sizes[2] / 2;
    const int* src = edge;
    const int* dst = edge + E;

    int node_blocks32 = (N_NODES + 31) / 32;
    int node_blocks64 = (N_NODES + 63) / 64;
    int eblocks = (E + 255) / 256;

    // device-global ping-pong buffers
    float *xA, *xB;
    cudaGetSymbolAddress((void**)&xA, g_xA);
    cudaGetSymbolAddress((void**)&xB, g_xB);

    // CSR build (edge structure only)
    zero_deg_kernel<<<NB_SCAN, 256>>>();
    hist_kernel<<<eblocks, 256>>>(dst, E);
    scan1_kernel<<<NB_SCAN, 256>>>();
    scan2_kernel<<<1, 512>>>();
    scan3_kernel<<<NB_SCAN, 256>>>(E);
    fill_kernel<<<eblocks, 256>>>(src, dst, E);

    // input MLP -> xA
    input_kernel<<<node_blocks32, 128>>>(x_num, x_cat, emb0, emb1, emb2, emb3, w_in, b_in, xA);

    // layer 1: xA -> xB ; layer 2: xB -> xA  (gather fused, ping-pong)
    sage_kernel<<<node_blocks64, 256>>>(xA, xB, w1l, b1l, w1r, g1, be1);
    sage_kernel<<<node_blocks64, 256>>>(xB, xA, w2l, b2l, w2r, g2, be2);

    head_kernel<<<node_blocks64, 256>>>(xA, wh1, bh1, wh2, bh2, out);
}